// round 9
// baseline (speedup 1.0000x reference)
#include <cuda_runtime.h>
#include <cuda_fp16.h>
#include <cstdint>

#define KK     9
#define IN_C   32
#define OUT_C  64
#define HWDIM  256
#define NTH    256

// smem: xs 390 rows (3*130) x 64B = 24960 ; ds 3*132 floats = 1584 ; pk 9*192 words = 6912
#define OFF_DS 24960
#define OFF_PK (OFF_DS + 1584)      // 26544
#define SMEM_BYTES 33792
#define OB_PITCH 132

// B fragments packed so lane (g,cl) reads one uint4 at (o*16 + cl*4) words:
// word w at row o:  cp = (w&3)*4 + (w>>2)
//   -> v.x = ks0 b0, v.y = ks0 b1, v.z = ks1 b0, v.w = ks1 b1
__device__ uint32_t g_wfrag[KK * 3 * OUT_C * 16];

__global__ void prep_weights(const float* __restrict__ w0,
                             const float* __restrict__ w1,
                             const float* __restrict__ w2) {
    int idx = blockIdx.x * blockDim.x + threadIdx.x;
    if (idx >= KK * 3 * OUT_C * 16) return;
    int p = idx / 3072;
    int r = idx % 3072;
    int i = r >> 10;
    int o = (r >> 4) & 63;
    int w = r & 15;
    int cp = (w & 3) * 4 + (w >> 2);
    const float* wsrc = (i == 0) ? w0 : (i == 1) ? w1 : w2;
    float v0 = wsrc[(o * IN_C + 2 * cp) * KK + p];
    float v1 = wsrc[(o * IN_C + 2 * cp + 1) * KK + p];
    __half2 hh = __halves2half2(__float2half(v0), __float2half(v1));
    g_wfrag[idx] = *(uint32_t*)&hh;
}

__device__ __forceinline__ void mma_f16(float* d, uint32_t a0, uint32_t a1,
                                        uint32_t a2, uint32_t a3,
                                        uint32_t b0, uint32_t b1) {
    asm volatile(
        "mma.sync.aligned.m16n8k16.row.col.f32.f16.f16.f32 "
        "{%0,%1,%2,%3}, {%4,%5,%6,%7}, {%8,%9}, {%0,%1,%2,%3};"
        : "+f"(d[0]), "+f"(d[1]), "+f"(d[2]), "+f"(d[3])
        : "r"(a0), "r"(a1), "r"(a2), "r"(a3), "r"(b0), "r"(b1));
}

__device__ __forceinline__ uint32_t hmul2u(uint32_t a, uint32_t m) {
    __half2 r = __hmul2(*(__half2*)&a, *(__half2*)&m);
    return *(uint32_t*)&r;
}

__global__ void __launch_bounds__(NTH, 3)
conv25d_v4(const float* __restrict__ x,
           const float* __restrict__ disp,
           const float* __restrict__ fxp,
           const float* __restrict__ blp,
           float* __restrict__ out) {
    __shared__ __align__(16) char smem[SMEM_BYTES];
    float*    ds  = (float*)(smem + OFF_DS);
    uint32_t* pkw = (uint32_t*)(smem + OFF_PK);

    const int tid  = threadIdx.x;
    const int lane = tid & 31;
    const int wrp  = tid >> 5;
    const int g    = lane >> 2;
    const int cl   = lane & 3;
    const int jb   = (wrp & 3) << 5;
    const int obase = (wrp >> 2) << 5;

    const int b   = blockIdx.x;          // 1024 CTAs
    const int n   = b >> 9;
    const int rem = b & 511;
    const int h   = rem >> 1;
    const int wb  = (rem & 1) << 7;

    const float* xb = x + (size_t)n * IN_C * (HWDIM * HWDIM);
    const float* db = disp + (size_t)n * (HWDIM * HWDIM);

    // ---- stage disp rows ----
    for (int e = tid; e < 3 * 130; e += NTH) {
        int di = e / 130, j = e % 130;
        int gy = h + di - 1, gx = wb - 1 + j;
        float v = 0.0f;
        if (gy >= 0 && gy < HWDIM && gx >= 0 && gx < HWDIM) v = db[gy * HWDIM + gx];
        ds[di * 132 + j] = v;
    }

    // ---- stage x (fp16, 64B rows, word pos = (cp&3)*4 + (cp>>2), no XOR) ----
    for (int t = wrp; t < 6 * 33; t += 8) {
        int plane = t / 33;
        int jb4   = (t % 33) * 4;
        int di = plane >> 1, cph = plane & 1;
        int cp = cph * 8 + g;
        int j  = jb4 + cl;
        if (j < 130) {
            int gy = h + di - 1, gx = wb - 1 + j;
            float v0 = 0.0f, v1 = 0.0f;
            if (gy >= 0 && gy < HWDIM && gx >= 0 && gx < HWDIM) {
                v0 = xb[(2 * cp) * (HWDIM * HWDIM) + gy * HWDIM + gx];
                v1 = xb[(2 * cp + 1) * (HWDIM * HWDIM) + gy * HWDIM + gx];
            }
            __half2 hh = __halves2half2(__float2half(v0), __float2half(v1));
            int row = di * 130 + j;
            int pos = (cp & 3) * 4 + (cp >> 2);
            *(uint32_t*)(smem + row * 64 + pos * 4) = *(uint32_t*)&hh;
        }
    }
    __syncthreads();

    // ---- precompute ALL 27 masks (bit-exact fp32); thread-halves split p ----
    {
        const int px = tid & 127;
        const float fxv = fxp[n];
        const float bf  = __fmul_rn(blp[n], fxv);
        const float dC  = ds[132 + 1 + px];
        const bool validC = (dC != 0.0f);
        const float depthC = __fdiv_rn(bf, fminf(fmaxf(validC ? dC : 0.0f, 0.01f), 256.0f));
        const float grv    = __fdiv_rn(__fmul_rn(16.0f, depthC), fxv);
        const float halfv  = __fmul_rn(grv, 0.5f);
        const bool lo = ((px >> 3) & 1) == 0;
        const int widx = ((px >> 4) << 3) | (px & 7);
        const int p0 = (tid < 128) ? 0 : 5;
        const int p1 = (tid < 128) ? 5 : 9;
        for (int p = p0; p < p1; p++) {
            int di = p / 3, dj = p % 3;
            float dp = ds[di * 132 + dj + px];
            const bool valid = (dp != 0.0f) && validC;
            const float depth = __fdiv_rn(bf, fminf(fmaxf(valid ? dp : 0.0f, 0.01f), 256.0f));
            float m[3];
            m[0] = (fabsf(__fsub_rn(depth, __fadd_rn(depthC, grv))) <= halfv) ? 1.0f : 0.0f;
            const float ind = (fabsf(__fsub_rn(depth, depthC)) <= halfv) ? 1.0f : 0.0f;
            m[1] = valid ? ind : 1.0f;
            m[2] = (fabsf(__fsub_rn(depth, __fsub_rn(depthC, grv))) <= halfv) ? 1.0f : 0.0f;
#pragma unroll
            for (int i = 0; i < 3; i++) {
                float pm = __shfl_xor_sync(0xffffffffu, m[i], 8);
                if (lo) {
                    __half2 hh = __halves2half2(__float2half(m[i]), __float2half(pm));
                    pkw[p * 192 + i * 64 + widx] = *(uint32_t*)&hh;
                }
            }
        }
    }
    __syncthreads();

    // ---- barrier-free main loop ----
    float acc[2][4][4];
#pragma unroll
    for (int mt = 0; mt < 2; mt++)
#pragma unroll
        for (int n8 = 0; n8 < 4; n8++)
#pragma unroll
            for (int q = 0; q < 4; q++) acc[mt][n8][q] = 0.0f;

#pragma unroll 1
    for (int p = 0; p < KK; p++) {
        const int di = p / 3, dj = p % 3;

        uint32_t pw[3][2];
        bool sk[3];
#pragma unroll
        for (int i = 0; i < 3; i++) {
            pw[i][0] = pkw[p * 192 + i * 64 + (jb >> 5) * 16 + g];
            pw[i][1] = pkw[p * 192 + i * 64 + (jb >> 5) * 16 + 8 + g];
            sk[i] = !__any_sync(0xffffffffu, (pw[i][0] | pw[i][1]) != 0u);
        }
        if (sk[0] && sk[1] && sk[2]) continue;

        // A fragments: 4 LDS.128, each uint4 = (ks0 a0w, ks0 a2w, ks1 a0w, ks1 a2w)
        const int rowb = di * 130 + dj + jb;
        uint4 vL[2], vH[2];
#pragma unroll
        for (int mt = 0; mt < 2; mt++) {
            vL[mt] = *(const uint4*)(smem + (rowb + mt * 16 + g) * 64 + cl * 16);
            vH[mt] = *(const uint4*)(smem + (rowb + mt * 16 + g + 8) * 64 + cl * 16);
        }

#pragma unroll
        for (int i = 0; i < 3; i++) {
            if (sk[i]) continue;
            // B fragments: 4 LDG.128
            const uint4* wf = (const uint4*)(g_wfrag + ((size_t)(p * 3 + i) * 64 + obase) * 16);
            uint4 bv[4];
#pragma unroll
            for (int n8 = 0; n8 < 4; n8++)
                bv[n8] = wf[(n8 * 8 + g) * 4 + cl];

#pragma unroll
            for (int mt = 0; mt < 2; mt++) {
                __half2 pp = *(__half2*)&pw[i][mt];
                __half2 l2 = __half2half2(__low2half(pp));
                __half2 h2 = __half2half2(__high2half(pp));
                uint32_t ml = *(uint32_t*)&l2, mh = *(uint32_t*)&h2;
                // ks0
                uint32_t a0 = hmul2u(vL[mt].x, ml);
                uint32_t a1 = hmul2u(vH[mt].x, mh);
                uint32_t a2 = hmul2u(vL[mt].y, ml);
                uint32_t a3 = hmul2u(vH[mt].y, mh);
#pragma unroll
                for (int n8 = 0; n8 < 4; n8++)
                    mma_f16(acc[mt][n8], a0, a1, a2, a3, bv[n8].x, bv[n8].y);
                // ks1
                a0 = hmul2u(vL[mt].z, ml);
                a1 = hmul2u(vH[mt].z, mh);
                a2 = hmul2u(vL[mt].w, ml);
                a3 = hmul2u(vH[mt].w, mh);
#pragma unroll
                for (int n8 = 0; n8 < 4; n8++)
                    mma_f16(acc[mt][n8], a0, a1, a2, a3, bv[n8].z, bv[n8].w);
            }
        }
    }

    // ---- epilogue: acc -> smem transpose -> coalesced float4 stores ----
    __syncthreads();
    float* obuf = (float*)smem;   // [o][j], pitch 132 (overlays everything)
#pragma unroll
    for (int mt = 0; mt < 2; mt++) {
#pragma unroll
        for (int n8 = 0; n8 < 4; n8++) {
            int o = obase + n8 * 8 + cl * 2;
            int j = jb + mt * 16 + g;
            obuf[o * OB_PITCH + j]           = acc[mt][n8][0];
            obuf[(o + 1) * OB_PITCH + j]     = acc[mt][n8][1];
            obuf[o * OB_PITCH + j + 8]       = acc[mt][n8][2];
            obuf[(o + 1) * OB_PITCH + j + 8] = acc[mt][n8][3];
        }
    }
    __syncthreads();
#pragma unroll
    for (int it = 0; it < 8; it++) {
        int e  = tid + it * NTH;
        int o  = e >> 5;
        int j4 = e & 31;
        float4 v = *(const float4*)&obuf[o * OB_PITCH + j4 * 4];
        *(float4*)&out[((size_t)(n * OUT_C + o)) * (HWDIM * HWDIM)
                       + h * HWDIM + wb + j4 * 4] = v;
    }
}

extern "C" void kernel_launch(void* const* d_in, const int* in_sizes, int n_in,
                              void* d_out, int out_size) {
    const float* x    = (const float*)d_in[0];
    const float* disp = (const float*)d_in[1];
    const float* fx   = (const float*)d_in[2];
    const float* bl   = (const float*)d_in[3];
    const float* w0   = (const float*)d_in[4];
    const float* w1   = (const float*)d_in[5];
    const float* w2   = (const float*)d_in[6];
    float* out = (float*)d_out;

    prep_weights<<<(KK * 3 * OUT_C * 16 + 255) / 256, 256>>>(w0, w1, w2);
    conv25d_v4<<<1024, NTH>>>(x, disp, fx, bl, out);
}

// round 10
// speedup vs baseline: 1.0234x; 1.0234x over previous
#include <cuda_runtime.h>
#include <cuda_fp16.h>
#include <cstdint>

#define KK     9
#define IN_C   32
#define OUT_C  64
#define HWDIM  256
#define NTH    512

// smem: xs 390 rows (3*130) x 64B = 24960 ; ds 3*132 floats = 1584 ; pk 9*192 words = 6912
#define OFF_DS 24960
#define OFF_PK (OFF_DS + 1584)      // 26544
#define SMEM_BYTES 33792            // also covers epilogue obuf 64*132*4
#define OB_PITCH 132

// B fragments (R8 layout): g_wfrag[((p*3+i)*64 + o)*16 + w], w = ks*8 + cl*2 + sub
//   <-> cp = ks*8 + cl + sub*4
__device__ uint32_t g_wfrag[KK * 3 * OUT_C * 16];

__global__ void prep_weights(const float* __restrict__ w0,
                             const float* __restrict__ w1,
                             const float* __restrict__ w2) {
    int idx = blockIdx.x * blockDim.x + threadIdx.x;
    if (idx >= KK * 3 * OUT_C * 16) return;
    int p = idx / 3072;
    int r = idx % 3072;
    int i = r >> 10;
    int o = (r >> 4) & 63;
    int w = r & 15;
    int ks = w >> 3, clw = (w >> 1) & 3, sub = w & 1;
    int cp = ks * 8 + clw + sub * 4;
    const float* wsrc = (i == 0) ? w0 : (i == 1) ? w1 : w2;
    float v0 = wsrc[(o * IN_C + 2 * cp) * KK + p];
    float v1 = wsrc[(o * IN_C + 2 * cp + 1) * KK + p];
    __half2 hh = __halves2half2(__float2half(v0), __float2half(v1));
    g_wfrag[idx] = *(uint32_t*)&hh;
}

__device__ __forceinline__ void mma_f16(float* d, uint32_t a0, uint32_t a1,
                                        uint32_t a2, uint32_t a3,
                                        uint32_t b0, uint32_t b1) {
    asm volatile(
        "mma.sync.aligned.m16n8k16.row.col.f32.f16.f16.f32 "
        "{%0,%1,%2,%3}, {%4,%5,%6,%7}, {%8,%9}, {%0,%1,%2,%3};"
        : "+f"(d[0]), "+f"(d[1]), "+f"(d[2]), "+f"(d[3])
        : "r"(a0), "r"(a1), "r"(a2), "r"(a3), "r"(b0), "r"(b1));
}

__device__ __forceinline__ uint32_t hmul2u(uint32_t a, uint32_t m) {
    __half2 r = __hmul2(*(__half2*)&a, *(__half2*)&m);
    return *(uint32_t*)&r;
}

__global__ void __launch_bounds__(NTH, 2)
conv25d_w16(const float* __restrict__ x,
            const float* __restrict__ disp,
            const float* __restrict__ fxp,
            const float* __restrict__ blp,
            float* __restrict__ out) {
    __shared__ __align__(16) char smem[SMEM_BYTES];
    float*    ds  = (float*)(smem + OFF_DS);
    uint32_t* pkw = (uint32_t*)(smem + OFF_PK);

    const int tid  = threadIdx.x;
    const int lane = tid & 31;
    const int wrp  = tid >> 5;           // 0..15
    const int g    = lane >> 2;
    const int cl   = lane & 3;
    const int mw   = wrp & 7;            // M16 group (16 px)
    const int obase = (wrp >> 3) << 5;   // N half
    const int jb   = mw << 4;

    const int b   = blockIdx.x;          // 1024 CTAs
    const int n   = b >> 9;
    const int rem = b & 511;
    const int h   = rem >> 1;
    const int wb  = (rem & 1) << 7;

    const float* xb = x + (size_t)n * IN_C * (HWDIM * HWDIM);
    const float* db = disp + (size_t)n * (HWDIM * HWDIM);

    // ---- stage disp rows ----
    for (int e = tid; e < 3 * 130; e += NTH) {
        int di = e / 130, j = e % 130;
        int gy = h + di - 1, gx = wb - 1 + j;
        float v = 0.0f;
        if (gy >= 0 && gy < HWDIM && gx >= 0 && gx < HWDIM) v = db[gy * HWDIM + gx];
        ds[di * 132 + j] = v;
    }

    // ---- stage x (fp16, 64B rows, word pos = (cp&3)*4 + (cp>>2)) ----
    for (int t = wrp; t < 6 * 33; t += 16) {
        int plane = t / 33;
        int jb4   = (t % 33) * 4;
        int di = plane >> 1, cph = plane & 1;
        int cp = cph * 8 + g;
        int j  = jb4 + cl;
        if (j < 130) {
            int gy = h + di - 1, gx = wb - 1 + j;
            float v0 = 0.0f, v1 = 0.0f;
            if (gy >= 0 && gy < HWDIM && gx >= 0 && gx < HWDIM) {
                v0 = xb[(2 * cp) * (HWDIM * HWDIM) + gy * HWDIM + gx];
                v1 = xb[(2 * cp + 1) * (HWDIM * HWDIM) + gy * HWDIM + gx];
            }
            __half2 hh = __halves2half2(__float2half(v0), __float2half(v1));
            int row = di * 130 + j;
            int pos = (cp & 3) * 4 + (cp >> 2);
            *(uint32_t*)(smem + row * 64 + pos * 4) = *(uint32_t*)&hh;
        }
    }
    __syncthreads();

    // ---- precompute ALL 27 masks (bit-exact fp32); 4 thread-groups split p ----
    {
        const int px = tid & 127;
        const int grp = tid >> 7;                  // 0..3
        const float fxv = fxp[n];
        const float bf  = __fmul_rn(blp[n], fxv);
        const float dC  = ds[132 + 1 + px];
        const bool validC = (dC != 0.0f);
        const float depthC = __fdiv_rn(bf, fminf(fmaxf(validC ? dC : 0.0f, 0.01f), 256.0f));
        const float grv    = __fdiv_rn(__fmul_rn(16.0f, depthC), fxv);
        const float halfv  = __fmul_rn(grv, 0.5f);
        const bool lo = ((px >> 3) & 1) == 0;
        const int widx = ((px >> 4) << 3) | (px & 7);   // mt16 group * 8 + g
        const int pstart[5] = {0, 2, 4, 6, 9};
        for (int p = pstart[grp]; p < pstart[grp + 1]; p++) {
            int di = p / 3, dj = p % 3;
            float dp = ds[di * 132 + dj + px];
            const bool valid = (dp != 0.0f) && validC;
            const float depth = __fdiv_rn(bf, fminf(fmaxf(valid ? dp : 0.0f, 0.01f), 256.0f));
            float m[3];
            m[0] = (fabsf(__fsub_rn(depth, __fadd_rn(depthC, grv))) <= halfv) ? 1.0f : 0.0f;
            const float ind = (fabsf(__fsub_rn(depth, depthC)) <= halfv) ? 1.0f : 0.0f;
            m[1] = valid ? ind : 1.0f;
            m[2] = (fabsf(__fsub_rn(depth, __fsub_rn(depthC, grv))) <= halfv) ? 1.0f : 0.0f;
#pragma unroll
            for (int i = 0; i < 3; i++) {
                float pm = __shfl_xor_sync(0xffffffffu, m[i], 8);
                if (lo) {
                    __half2 hh = __halves2half2(__float2half(m[i]), __float2half(pm));
                    pkw[p * 192 + i * 64 + widx] = *(uint32_t*)&hh;
                }
            }
        }
    }
    __syncthreads();

    // ---- barrier-free main loop: warp tile M16 x N32 ----
    float acc[4][4];
#pragma unroll
    for (int n8 = 0; n8 < 4; n8++)
#pragma unroll
        for (int q = 0; q < 4; q++) acc[n8][q] = 0.0f;

#pragma unroll 1
    for (int p = 0; p < KK; p++) {
        const int di = p / 3, dj = p % 3;

        uint32_t pw[3];
        bool sk[3];
#pragma unroll
        for (int i = 0; i < 3; i++) {
            pw[i] = pkw[p * 192 + i * 64 + mw * 8 + g];
            sk[i] = !__any_sync(0xffffffffu, pw[i] != 0u);
        }
        if (sk[0] && sk[1] && sk[2]) continue;

        // A fragments: 2 LDS.128 (uint4 = ks0 a0w, ks0 a2w, ks1 a0w, ks1 a2w)
        const int rowb = di * 130 + dj + jb;
        const uint4 vL = *(const uint4*)(smem + (rowb + g) * 64 + cl * 16);
        const uint4 vH = *(const uint4*)(smem + (rowb + g + 8) * 64 + cl * 16);

#pragma unroll
        for (int i = 0; i < 3; i++) {
            if (sk[i]) continue;
            const uint32_t* wf = g_wfrag + ((size_t)(p * 3 + i) * 64 + obase) * 16;

            __half2 pp = *(__half2*)&pw[i];
            __half2 l2 = __half2half2(__low2half(pp));
            __half2 h2 = __half2half2(__high2half(pp));
            const uint32_t ml = *(uint32_t*)&l2, mh = *(uint32_t*)&h2;

            // ks0
            uint32_t a0 = hmul2u(vL.x, ml);
            uint32_t a1 = hmul2u(vH.x, mh);
            uint32_t a2 = hmul2u(vL.y, ml);
            uint32_t a3 = hmul2u(vH.y, mh);
#pragma unroll
            for (int n8 = 0; n8 < 4; n8++) {
                uint2 bv = *(const uint2*)(wf + (n8 * 8 + g) * 16 + cl * 2);
                mma_f16(acc[n8], a0, a1, a2, a3, bv.x, bv.y);
            }
            // ks1
            a0 = hmul2u(vL.z, ml);
            a1 = hmul2u(vH.z, mh);
            a2 = hmul2u(vL.w, ml);
            a3 = hmul2u(vH.w, mh);
#pragma unroll
            for (int n8 = 0; n8 < 4; n8++) {
                uint2 bv = *(const uint2*)(wf + (n8 * 8 + g) * 16 + 8 + cl * 2);
                mma_f16(acc[n8], a0, a1, a2, a3, bv.x, bv.y);
            }
        }
    }

    // ---- epilogue: acc -> smem transpose -> coalesced float4 stores ----
    __syncthreads();
    float* obuf = (float*)smem;   // [o][j], pitch 132
#pragma unroll
    for (int n8 = 0; n8 < 4; n8++) {
        int o = obase + n8 * 8 + cl * 2;
        int j = jb + g;
        obuf[o * OB_PITCH + j]           = acc[n8][0];
        obuf[(o + 1) * OB_PITCH + j]     = acc[n8][1];
        obuf[o * OB_PITCH + j + 8]       = acc[n8][2];
        obuf[(o + 1) * OB_PITCH + j + 8] = acc[n8][3];
    }
    __syncthreads();
#pragma unroll
    for (int it = 0; it < 4; it++) {
        int e  = tid + it * NTH;   // (o, j4): 64 x 32
        int o  = e >> 5;
        int j4 = e & 31;
        float4 v = *(const float4*)&obuf[o * OB_PITCH + j4 * 4];
        *(float4*)&out[((size_t)(n * OUT_C + o)) * (HWDIM * HWDIM)
                       + h * HWDIM + wb + j4 * 4] = v;
    }
}

extern "C" void kernel_launch(void* const* d_in, const int* in_sizes, int n_in,
                              void* d_out, int out_size) {
    const float* x    = (const float*)d_in[0];
    const float* disp = (const float*)d_in[1];
    const float* fx   = (const float*)d_in[2];
    const float* bl   = (const float*)d_in[3];
    const float* w0   = (const float*)d_in[4];
    const float* w1   = (const float*)d_in[5];
    const float* w2   = (const float*)d_in[6];
    float* out = (float*)d_out;

    prep_weights<<<(KK * 3 * OUT_C * 16 + 255) / 256, 256>>>(w0, w1, w2);
    conv25d_w16<<<1024, NTH>>>(x, disp, fx, bl, out);
}